// round 10
// baseline (speedup 1.0000x reference)
#include <cuda_runtime.h>
#include <mma.h>
using namespace nvcuda;

#define DIM   1024
#define TOK   71
#define BATCH 1024
#define BT    (BATCH * TOK)   /* 72704 = 568*128 */
#define LAYERS 12

__device__ float g_x  [(size_t)BT * DIM];
__device__ float g_y  [3 * (size_t)BT * DIM];
__device__ float g_att[(size_t)BATCH * TOK * 72];
__device__ float g_h  [(size_t)BT * 2 * DIM];
__device__ float g_h2 [(size_t)BT * DIM];

__device__ __forceinline__ float blockSum256(float v, float* buf) {
    #pragma unroll
    for (int o = 16; o > 0; o >>= 1) v += __shfl_xor_sync(0xffffffffu, v, o);
    int lane = threadIdx.x & 31, w = threadIdx.x >> 5;
    if (lane == 0) buf[w] = v;
    __syncthreads();
    if (threadIdx.x == 0) { float s = 0.f;
        #pragma unroll
        for (int i = 0; i < 8; i++) s += buf[i];
        buf[0] = s; }
    __syncthreads();
    float r = buf[0];
    __syncthreads();
    return r;
}

// ---- embedding + LN: one block per (b,t) row, 256 thr x 4 elems ----
__global__ __launch_bounds__(256) void embed_ln_kernel(
    const int* __restrict__ fen, const int* __restrict__ mv,
    const float* __restrict__ rank_emb, const float* __restrict__ file_emb,
    const float* __restrict__ fen_emb,  const float* __restrict__ move_emb,
    const float* __restrict__ g, const float* __restrict__ bb,
    float* __restrict__ X)
{
    __shared__ float buf[8];
    int row = blockIdx.x, b = row / TOK, t = row % TOK, d0 = threadIdx.x * 4;
    float e[4];
    if (t < 64) {
        int i1 = fen[b * 133 + t], i2 = fen[b * 133 + 64 + t];
        float4 f1 = *(const float4*)(fen_emb  + (size_t)i1 * DIM + d0);
        float4 f2 = *(const float4*)(fen_emb  + (size_t)i2 * DIM + d0);
        float4 rr = *(const float4*)(rank_emb + (size_t)(t >> 3) * DIM + d0);
        float4 ff = *(const float4*)(file_emb + (size_t)(t & 7)  * DIM + d0);
        e[0] = 0.5f * (f1.x + f2.x + rr.x + ff.x);
        e[1] = 0.5f * (f1.y + f2.y + rr.y + ff.y);
        e[2] = 0.5f * (f1.z + f2.z + rr.z + ff.z);
        e[3] = 0.5f * (f1.w + f2.w + rr.w + ff.w);
    } else if (t < 69) {
        int i1 = fen[b * 133 + 64 + t];
        float4 f1 = *(const float4*)(fen_emb + (size_t)i1 * DIM + d0);
        e[0] = f1.x; e[1] = f1.y; e[2] = f1.z; e[3] = f1.w;
    } else {
        int j = t - 69, p = mv[b * 2 + j];
        float4 rr = *(const float4*)(rank_emb + (size_t)(p >> 3) * DIM + d0);
        float4 ff = *(const float4*)(file_emb + (size_t)(p & 7)  * DIM + d0);
        float4 mm = *(const float4*)(move_emb + (size_t)j * DIM + d0);
        e[0] = 0.58f * (rr.x + ff.x + mm.x);
        e[1] = 0.58f * (rr.y + ff.y + mm.y);
        e[2] = 0.58f * (rr.z + ff.z + mm.z);
        e[3] = 0.58f * (rr.w + ff.w + mm.w);
    }
    float s  = blockSum256(e[0] + e[1] + e[2] + e[3], buf);
    float sq = blockSum256(e[0]*e[0] + e[1]*e[1] + e[2]*e[2] + e[3]*e[3], buf);
    float m = s * (1.f / DIM);
    float rs = rsqrtf(fmaxf(sq * (1.f / DIM) - m * m, 0.f) + 1e-5f);
    float4 gg = *(const float4*)(g + d0), bv = *(const float4*)(bb + d0);
    float4 o;
    o.x = (e[0] - m) * rs * gg.x + bv.x;
    o.y = (e[1] - m) * rs * gg.y + bv.y;
    o.z = (e[2] - m) * rs * gg.z + bv.z;
    o.w = (e[3] - m) * rs * gg.w + bv.w;
    *(float4*)(X + (size_t)row * DIM + d0) = o;
}

// ---- in-place row LN ----
__global__ __launch_bounds__(256) void ln_rows_kernel(
    float* __restrict__ data, const float* __restrict__ g, const float* __restrict__ bb)
{
    __shared__ float buf[8];
    size_t base = (size_t)blockIdx.x * DIM;
    int d0 = threadIdx.x * 4;
    float4 v = *(float4*)(data + base + d0);
    float s  = blockSum256(v.x + v.y + v.z + v.w, buf);
    float sq = blockSum256(v.x*v.x + v.y*v.y + v.z*v.z + v.w*v.w, buf);
    float m = s * (1.f / DIM);
    float rs = rsqrtf(fmaxf(sq * (1.f / DIM) - m * m, 0.f) + 1e-5f);
    float4 gg = *(const float4*)(g + d0), bv = *(const float4*)(bb + d0);
    v.x = (v.x - m) * rs * gg.x + bv.x;
    v.y = (v.y - m) * rs * gg.y + bv.y;
    v.z = (v.z - m) * rs * gg.z + bv.z;
    v.w = (v.w - m) * rs * gg.w + bv.w;
    *(float4*)(data + base + d0) = v;
}

// ---- x = 0.7*(x + LN(y)) ----
__global__ __launch_bounds__(256) void ln_res_kernel(
    float* __restrict__ X, const float* __restrict__ Y,
    const float* __restrict__ g, const float* __restrict__ bb)
{
    __shared__ float buf[8];
    size_t base = (size_t)blockIdx.x * DIM;
    int d0 = threadIdx.x * 4;
    float4 y = *(const float4*)(Y + base + d0);
    float s  = blockSum256(y.x + y.y + y.z + y.w, buf);
    float sq = blockSum256(y.x*y.x + y.y*y.y + y.z*y.z + y.w*y.w, buf);
    float m = s * (1.f / DIM);
    float rs = rsqrtf(fmaxf(sq * (1.f / DIM) - m * m, 0.f) + 1e-5f);
    float4 gg = *(const float4*)(g + d0), bv = *(const float4*)(bb + d0);
    float4 x = *(float4*)(X + base + d0);
    x.x = 0.7f * (x.x + ((y.x - m) * rs * gg.x + bv.x));
    x.y = 0.7f * (x.y + ((y.y - m) * rs * gg.y + bv.y));
    x.z = 0.7f * (x.z + ((y.z - m) * rs * gg.z + bv.z));
    x.w = 0.7f * (x.w + ((y.w - m) * rs * gg.w + bv.w));
    *(float4*)(X + base + d0) = x;
}

// ---- tf32 wmma GEMM: C = A[M,K] @ B, fp32 acc.
//   TRANSB=false: B = W[K,N] row-major; TRANSB=true: B = W[N,K] (C = A @ W^T).
//   LEAKY: fused leaky_relu(0.2). 128x128x16 tile, 8 warps (4x2). ----
template <bool TRANSB, bool LEAKY>
__global__ __launch_bounds__(256) void gemm_tf32(
    const float* __restrict__ A, const float* __restrict__ W,
    float* __restrict__ C, int M, int N, int K)
{
    __shared__ float As[128 * 24];
    __shared__ float Bs[128 * 24];   // TRANSB: [128][16] ld24; else [16][128] ld136
    if (gridDim.z > 1) {
        W += (size_t)blockIdx.z * K * N;
        C += (size_t)blockIdx.z * M * N;
    }
    const int m0 = blockIdx.y * 128, n0 = blockIdx.x * 128;
    const int tid = threadIdx.x, warp = tid >> 5;
    const int wm = warp & 3, wn = warp >> 2;

    wmma::fragment<wmma::accumulator, 16, 16, 8, float> acc[2][4];
    #pragma unroll
    for (int i = 0; i < 2; i++)
        #pragma unroll
        for (int j = 0; j < 4; j++) wmma::fill_fragment(acc[i][j], 0.f);

    for (int k0 = 0; k0 < K; k0 += 16) {
        #pragma unroll
        for (int q = 0; q < 2; q++) {
            int id = tid + q * 256, r = id >> 2, c = (id & 3) * 4;
            float4 v = *(const float4*)(A + (size_t)(m0 + r) * K + k0 + c);
            As[r * 24 + c + 0] = wmma::__float_to_tf32(v.x);
            As[r * 24 + c + 1] = wmma::__float_to_tf32(v.y);
            As[r * 24 + c + 2] = wmma::__float_to_tf32(v.z);
            As[r * 24 + c + 3] = wmma::__float_to_tf32(v.w);
        }
        if constexpr (TRANSB) {
            #pragma unroll
            for (int q = 0; q < 2; q++) {
                int id = tid + q * 256, r = id >> 2, c = (id & 3) * 4;
                float4 v = *(const float4*)(W + (size_t)(n0 + r) * K + k0 + c);
                Bs[r * 24 + c + 0] = wmma::__float_to_tf32(v.x);
                Bs[r * 24 + c + 1] = wmma::__float_to_tf32(v.y);
                Bs[r * 24 + c + 2] = wmma::__float_to_tf32(v.z);
                Bs[r * 24 + c + 3] = wmma::__float_to_tf32(v.w);
            }
        } else {
            #pragma unroll
            for (int q = 0; q < 2; q++) {
                int id = tid + q * 256, r = id >> 5, c = (id & 31) * 4;
                float4 v = *(const float4*)(W + (size_t)(k0 + r) * N + n0 + c);
                Bs[r * 136 + c + 0] = wmma::__float_to_tf32(v.x);
                Bs[r * 136 + c + 1] = wmma::__float_to_tf32(v.y);
                Bs[r * 136 + c + 2] = wmma::__float_to_tf32(v.z);
                Bs[r * 136 + c + 3] = wmma::__float_to_tf32(v.w);
            }
        }
        __syncthreads();
        #pragma unroll
        for (int ks = 0; ks < 16; ks += 8) {
            wmma::fragment<wmma::matrix_a, 16, 16, 8, wmma::precision::tf32, wmma::row_major> af[2];
            wmma::load_matrix_sync(af[0], As + (wm * 32 + 0)  * 24 + ks, 24);
            wmma::load_matrix_sync(af[1], As + (wm * 32 + 16) * 24 + ks, 24);
            #pragma unroll
            for (int j = 0; j < 4; j++) {
                if constexpr (TRANSB) {
                    wmma::fragment<wmma::matrix_b, 16, 16, 8, wmma::precision::tf32, wmma::col_major> bf;
                    wmma::load_matrix_sync(bf, Bs + (wn * 64 + j * 16) * 24 + ks, 24);
                    wmma::mma_sync(acc[0][j], af[0], bf, acc[0][j]);
                    wmma::mma_sync(acc[1][j], af[1], bf, acc[1][j]);
                } else {
                    wmma::fragment<wmma::matrix_b, 16, 16, 8, wmma::precision::tf32, wmma::row_major> bf;
                    wmma::load_matrix_sync(bf, Bs + ks * 136 + wn * 64 + j * 16, 136);
                    wmma::mma_sync(acc[0][j], af[0], bf, acc[0][j]);
                    wmma::mma_sync(acc[1][j], af[1], bf, acc[1][j]);
                }
            }
        }
        __syncthreads();
    }
    #pragma unroll
    for (int i = 0; i < 2; i++)
        #pragma unroll
        for (int j = 0; j < 4; j++) {
            if constexpr (LEAKY) {
                #pragma unroll
                for (int t = 0; t < acc[i][j].num_elements; t++) {
                    float x = acc[i][j].x[t];
                    acc[i][j].x[t] = x > 0.f ? x : 0.2f * x;
                }
            }
            wmma::store_matrix_sync(
                C + (size_t)(m0 + wm * 32 + i * 16) * N + n0 + wn * 64 + j * 16,
                acc[i][j], N, wmma::mem_row_major);
        }
}

// ---- scores + softmax per batch item ----
__global__ __launch_bounds__(256) void scores_softmax_kernel(
    const float* __restrict__ Q, const float* __restrict__ Km, float* __restrict__ ATT)
{
    __shared__ float sm[5280];          // qs[80][33] | ks[80][33]; reused as S[71][72]
    float* qs = sm;
    float* ks = sm + 2640;
    const int b = blockIdx.x, tid = threadIdx.x;
    const int tx = tid & 15, ty = tid >> 4;

    float acc[5][5];
    #pragma unroll
    for (int i = 0; i < 5; i++)
        #pragma unroll
        for (int j = 0; j < 5; j++) acc[i][j] = 0.f;

    for (int kc = 0; kc < DIM; kc += 32) {
        __syncthreads();
        for (int idx = tid; idx < TOK * 32; idx += 256) {
            int r = idx >> 5, c = idx & 31;
            size_t gb = ((size_t)b * TOK + r) * DIM + kc + c;
            qs[r * 33 + c] = Q[gb];
            ks[r * 33 + c] = Km[gb];
        }
        __syncthreads();
        #pragma unroll 8
        for (int kk = 0; kk < 32; kk++) {
            float qv[5], kv[5];
            #pragma unroll
            for (int i = 0; i < 5; i++) qv[i] = (ty + 16 * i < TOK) ? qs[(ty + 16 * i) * 33 + kk] : 0.f;
            #pragma unroll
            for (int j = 0; j < 5; j++) kv[j] = (tx + 16 * j < TOK) ? ks[(tx + 16 * j) * 33 + kk] : 0.f;
            #pragma unroll
            for (int i = 0; i < 5; i++)
                #pragma unroll
                for (int j = 0; j < 5; j++) acc[i][j] += qv[i] * kv[j];
        }
    }
    __syncthreads();
    #pragma unroll
    for (int i = 0; i < 5; i++)
        #pragma unroll
        for (int j = 0; j < 5; j++) {
            int r = ty + 16 * i, c = tx + 16 * j;
            if (r < TOK && c < TOK) sm[r * 72 + c] = acc[i][j] * 0.03125f;
        }
    __syncthreads();

    const int lane = tid & 31, w = tid >> 5;
    for (int r = w; r < TOK; r += 8) {
        float v[3], p[3], mx = -1e30f;
        #pragma unroll
        for (int q = 0; q < 3; q++) {
            int c = lane + q * 32;
            v[q] = (c < TOK) ? sm[r * 72 + c] : -1e30f;
            mx = fmaxf(mx, v[q]);
        }
        #pragma unroll
        for (int o = 16; o > 0; o >>= 1) mx = fmaxf(mx, __shfl_xor_sync(0xffffffffu, mx, o));
        float sum = 0.f;
        #pragma unroll
        for (int q = 0; q < 3; q++) {
            int c = lane + q * 32;
            p[q] = (c < TOK) ? __expf(v[q] - mx) : 0.f;
            sum += p[q];
        }
        #pragma unroll
        for (int o = 16; o > 0; o >>= 1) sum += __shfl_xor_sync(0xffffffffu, sum, o);
        float inv = 1.f / sum;
        #pragma unroll
        for (int q = 0; q < 3; q++) {
            int c = lane + q * 32;
            if (c < TOK) ATT[(size_t)b * (TOK * 72) + r * 72 + c] = p[q] * inv;
        }
    }
}

// ---- AO = ATT @ V ----
__global__ __launch_bounds__(128) void av_kernel(
    const float* __restrict__ ATT, const float* __restrict__ V, float* __restrict__ AO)
{
    __shared__ float att_s[TOK * 72];
    const int b = blockIdx.y;
    const int d = blockIdx.x * 128 + threadIdx.x;
    for (int i = threadIdx.x; i < TOK * TOK; i += 128) {
        int t = i / TOK, s = i - t * TOK;
        att_s[t * 72 + s] = ATT[(size_t)b * (TOK * 72) + t * 72 + s];
    }
    __syncthreads();
    float acc[TOK];
    #pragma unroll
    for (int t = 0; t < TOK; t++) acc[t] = 0.f;
    for (int s = 0; s < TOK; s++) {
        float vv = V[((size_t)b * TOK + s) * DIM + d];
        #pragma unroll
        for (int t = 0; t < TOK; t++) acc[t] += att_s[t * 72 + s] * vv;
    }
    #pragma unroll
    for (int t = 0; t < TOK; t++)
        AO[((size_t)b * TOK + t) * DIM + d] = acc[t];
}

// ---- head ----
__global__ __launch_bounds__(256) void head_kernel(
    const float* __restrict__ X, const float* __restrict__ w,
    const float* __restrict__ bias, float* __restrict__ out)
{
    __shared__ float buf[8];
    const int b = blockIdx.x;
    float s = 0.f;
    for (int i = threadIdx.x; i < 2 * DIM; i += 256) {
        float xv = (i < DIM) ? X[((size_t)b * TOK + 69) * DIM + i]
                             : X[((size_t)b * TOK + 70) * DIM + i - DIM];
        s += xv * w[i];
    }
    s = blockSum256(s, buf);
    if (threadIdx.x == 0) out[b] = 1.f / (1.f + __expf(-(s + bias[0])));
}

extern "C" void kernel_launch(void* const* d_in, const int* in_sizes, int n_in,
                              void* d_out, int out_size)
{
    const int*   fen       = (const int*)  d_in[0];
    const int*   mv        = (const int*)  d_in[1];
    const float* rank_emb  = (const float*)d_in[2];
    const float* file_emb  = (const float*)d_in[3];
    const float* fen_emb   = (const float*)d_in[4];
    const float* move_emb  = (const float*)d_in[5];
    const float* ln_emb_g  = (const float*)d_in[6];
    const float* ln_emb_b  = (const float*)d_in[7];
    const float* qkv       = (const float*)d_in[8];
    const float* ln_q_g    = (const float*)d_in[9];
    const float* ln_q_b    = (const float*)d_in[10];
    const float* ln_k_g    = (const float*)d_in[11];
    const float* ln_k_b    = (const float*)d_in[12];
    const float* ln_attn_g = (const float*)d_in[13];
    const float* ln_attn_b = (const float*)d_in[14];
    const float* lin1_w    = (const float*)d_in[15];
    const float* lin2_w    = (const float*)d_in[16];
    const float* ln_ff_g   = (const float*)d_in[17];
    const float* ln_ff_b   = (const float*)d_in[18];
    const float* out_w     = (const float*)d_in[19];
    const float* out_b     = (const float*)d_in[20];
    float* out = (float*)d_out;

    float *X, *Y, *ATT, *H, *H2;
    cudaGetSymbolAddress((void**)&X,   g_x);
    cudaGetSymbolAddress((void**)&Y,   g_y);
    cudaGetSymbolAddress((void**)&ATT, g_att);
    cudaGetSymbolAddress((void**)&H,   g_h);
    cudaGetSymbolAddress((void**)&H2,  g_h2);

    embed_ln_kernel<<<BT, 256>>>(fen, mv, rank_emb, file_emb, fen_emb, move_emb,
                                 ln_emb_g, ln_emb_b, X);

    for (int l = 0; l < LAYERS; l++) {
        // QKV: Y[n] = X @ qkv[l][n], W row-major [D,D], 3 slabs via grid.z
        gemm_tf32<false, false><<<dim3(DIM / 128, BT / 128, 3), 256>>>(
            X, qkv + (size_t)l * 3 * DIM * DIM, Y, BT, DIM, DIM);

        ln_rows_kernel<<<BT, 256>>>(Y,                    ln_q_g + l * DIM, ln_q_b + l * DIM);
        ln_rows_kernel<<<BT, 256>>>(Y + (size_t)BT * DIM, ln_k_g + l * DIM, ln_k_b + l * DIM);

        scores_softmax_kernel<<<BATCH, 256>>>(Y, Y + (size_t)BT * DIM, ATT);
        av_kernel<<<dim3(DIM / 128, BATCH), 128>>>(ATT, Y + 2 * (size_t)BT * DIM, H2);

        ln_res_kernel<<<BT, 256>>>(X, H2, ln_attn_g + l * DIM, ln_attn_b + l * DIM);

        // FF: H = leaky(X @ lin1^T) [BT,2D]; H2 = leaky(H @ lin2^T) [BT,D]
        gemm_tf32<true, true><<<dim3(2 * DIM / 128, BT / 128, 1), 256>>>(
            X, lin1_w + (size_t)l * 2 * DIM * DIM, H, BT, 2 * DIM, DIM);
        gemm_tf32<true, true><<<dim3(DIM / 128, BT / 128, 1), 256>>>(
            H, lin2_w + (size_t)l * 2 * DIM * DIM, H2, BT, DIM, 2 * DIM);

        ln_res_kernel<<<BT, 256>>>(X, H2, ln_ff_g + l * DIM, ln_ff_b + l * DIM);
    }

    head_kernel<<<BATCH, 256>>>(X, out_w, out_b, out);
}